// round 9
// baseline (speedup 1.0000x reference)
#include <cuda_runtime.h>
#include <cuda_fp16.h>
#include <cstdint>
#include <cstring>

// out[n,o,p] = relu( sum_c fea[n,c,p] * W[o,c,0,4] + b[o] )
// GEMM per batch: D[512,4096] = Wc[512,2048] @ fea_n[2048,4096]
// fp16 mma.sync.m16n8k16, fp32 accumulate.
// B (fea) conversion fp32->fp16 is FUSED into the GEMM (LDG->cvt->STS),
// eliminating the 402MB convert round-trip of the previous version.

#define GM 512
#define GN 4096
#define GK 2048
#define NB 8

#define BM 128
#define BN 128
#define BK 32
#define ASTAGES 3
#define NITER (GK / BK)   // 64
#define NMB (GM / BM)     // 4
#define NPB (GN / BN)     // 32

// smem layout (bytes): padded rows for conflict-free ldmatrix
#define A_ROW_B 80                      // 32 halves (64B) + 16B pad
#define A_TILE_B (BM * A_ROW_B)         // 10240
#define B_ROW_B 272                     // 128 halves (256B) + 16B pad
#define B_TILE_B (BK * B_ROW_B)         // 8704
#define SMEM_B (ASTAGES * A_TILE_B + 2 * B_TILE_B)   // 48128

__device__ __align__(16) __half g_Wh[GM * GK];   // 2 MB packed Wc (fp16)

// ---------------------------------------------------------------------------
__device__ __forceinline__ uint32_t smem_u32(const void* p) {
    uint32_t a;
    asm("{ .reg .u64 t; cvta.to.shared.u64 t, %1; cvt.u32.u64 %0, t; }" : "=r"(a) : "l"(p));
    return a;
}
__device__ __forceinline__ void cp16(uint32_t dst, const void* src) {
    asm volatile("cp.async.cg.shared.global [%0], [%1], 16;" :: "r"(dst), "l"(src));
}
#define CP_COMMIT() asm volatile("cp.async.commit_group;" ::: "memory")
template <int N>
__device__ __forceinline__ void cp_wait() {
    asm volatile("cp.async.wait_group %0;" :: "n"(N) : "memory");
}

__device__ __forceinline__ void ldmA(uint32_t* r, uint32_t addr) {
    asm volatile("ldmatrix.sync.aligned.m8n8.x4.shared.b16 {%0,%1,%2,%3}, [%4];"
        : "=r"(r[0]), "=r"(r[1]), "=r"(r[2]), "=r"(r[3]) : "r"(addr));
}
__device__ __forceinline__ void ldmBT(uint32_t* r, uint32_t addr) {
    asm volatile("ldmatrix.sync.aligned.m8n8.x4.trans.shared.b16 {%0,%1,%2,%3}, [%4];"
        : "=r"(r[0]), "=r"(r[1]), "=r"(r[2]), "=r"(r[3]) : "r"(addr));
}
__device__ __forceinline__ void mma16816(float* c, const uint32_t* a, uint32_t b0, uint32_t b1) {
    asm volatile("mma.sync.aligned.m16n8k16.row.col.f32.f16.f16.f32 "
        "{%0,%1,%2,%3}, {%4,%5,%6,%7}, {%8,%9}, {%0,%1,%2,%3};"
        : "+f"(c[0]), "+f"(c[1]), "+f"(c[2]), "+f"(c[3])
        : "r"(a[0]), "r"(a[1]), "r"(a[2]), "r"(a[3]), "r"(b0), "r"(b1));
}
__device__ __forceinline__ uint32_t pkh2(float a, float b) {
    __half2 h = __floats2half2_rn(a, b);
    uint32_t u; memcpy(&u, &h, 4); return u;
}

// ---------------------------------------------------------------------------
// Pack Wc = W[:,:,0,4] -> fp16 row-major [M][K]
__global__ void pack_w_kernel(const float* __restrict__ W) {
    int i = blockIdx.x * blockDim.x + threadIdx.x;
    if (i < GM * GK) g_Wh[i] = __float2half_rn(W[(size_t)i * 9 + 4]);
}

// ---------------------------------------------------------------------------
__global__ __launch_bounds__(256, 2)
void gemm_kernel(const float* __restrict__ fea, const float* __restrict__ bias,
                 float* __restrict__ out) {
    extern __shared__ char smem[];
    const uint32_t sb  = smem_u32(smem);
    const uint32_t sbB = sb + ASTAGES * A_TILE_B;
    char* const smB = smem + ASTAGES * A_TILE_B;

    const int tid  = threadIdx.x;
    const int wid  = tid >> 5;
    const int lane = tid & 31;
    const int mblk = blockIdx.x, pblk = blockIdx.y, nb = blockIdx.z;
    const int wm = wid & 1;        // 2 warps in M (64 rows each)
    const int wn = wid >> 1;       // 4 warps in N (32 cols each)

    const __half* Asrc = g_Wh + (size_t)mblk * BM * GK;                // [m][k] fp16
    const float*  Bsrc = fea + (size_t)nb * GK * GN + pblk * BN;       // [k][n] fp32

    // ---- A cp.async mapping (2 chunks / thread / stage) ----
    const int aM  = wid * 8 + (lane & 7);      // A row (first of pair), +64 for second
    const int aKc = (lane >> 3) & 3;           // 16B chunk within 64B row

    auto issue_stageA = [&](int s, int kchunk) {
        const int k0 = kchunk * BK;
        uint32_t aBase = sb + s * A_TILE_B;
        cp16(aBase + aM * A_ROW_B + aKc * 16,
             Asrc + (size_t)aM * GK + k0 + aKc * 8);
        cp16(aBase + (aM + 64) * A_ROW_B + aKc * 16,
             Asrc + (size_t)(aM + 64) * GK + k0 + aKc * 8);
        CP_COMMIT();
    };

    // ---- B fused load+convert: thread reads 16 consecutive fp32, keeps 8 half2 ----
    const int bRow  = tid >> 3;                // 0..31 (k within chunk)
    const int bColF = (tid & 7) * 16;          // float column (0..112)

    uint4 hv0, hv1;                            // 16 halves, live across iterations
    auto ldgB = [&](int kc) {
        const float* p = Bsrc + ((size_t)kc * BK + bRow) * GN + bColF;
        float4 f0 = *(const float4*)(p);
        float4 f1 = *(const float4*)(p + 4);
        float4 f2 = *(const float4*)(p + 8);
        float4 f3 = *(const float4*)(p + 12);
        hv0 = make_uint4(pkh2(f0.x, f0.y), pkh2(f0.z, f0.w),
                         pkh2(f1.x, f1.y), pkh2(f1.z, f1.w));
        hv1 = make_uint4(pkh2(f2.x, f2.y), pkh2(f2.z, f2.w),
                         pkh2(f3.x, f3.y), pkh2(f3.z, f3.w));
    };
    auto stsB = [&](int buf) {
        char* d = smB + buf * B_TILE_B + bRow * B_ROW_B + bColF * 2;
        *(uint4*)(d)      = hv0;
        *(uint4*)(d + 16) = hv1;
    };

    float acc[4][4][4];
    #pragma unroll
    for (int mt = 0; mt < 4; ++mt)
        #pragma unroll
        for (int nt = 0; nt < 4; ++nt)
            #pragma unroll
            for (int j = 0; j < 4; ++j) acc[mt][nt][j] = 0.0f;

    // ---- prologue ----
    issue_stageA(0, 0);
    issue_stageA(1, 1);
    ldgB(0);
    stsB(0);          // chunk 0 -> buf 0 (consumed after first __syncthreads)
    ldgB(1);          // chunk 1 staged in registers

    const uint32_t aLdOff = (uint32_t)(wm * 64 + (lane & 15)) * A_ROW_B + ((lane >> 4) * 8) * 2;
    const uint32_t bLdOff = (uint32_t)(lane & 15) * B_ROW_B + (wn * 32 + (lane >> 4) * 8) * 2;

    for (int i = 0; i < NITER; ++i) {
        if (i < NITER - 1) cp_wait<1>(); else cp_wait<0>();
        __syncthreads();   // A(i) in smem; B STS(i) visible; compute(i-1) finished

        if (i + 2 < NITER) issue_stageA((i + 2) % ASTAGES, i + 2);
        if (i + 1 < NITER) stsB((i + 1) & 1);    // regs(chunk i+1) -> other buffer
        if (i + 2 < NITER) ldgB(i + 2);          // prefetch next chunk into regs

        const uint32_t aBase = sb + (i % ASTAGES) * A_TILE_B;
        const uint32_t bBase = sbB + (i & 1) * B_TILE_B;

        #pragma unroll
        for (int ks = 0; ks < 2; ++ks) {
            const int k0 = ks * 16;
            uint32_t afr[4][4];
            #pragma unroll
            for (int mt = 0; mt < 4; ++mt)
                ldmA(afr[mt], aBase + aLdOff + (uint32_t)mt * 16 * A_ROW_B + k0 * 2);
            uint32_t bfr[2][4];
            uint32_t bAddr = bBase + bLdOff + (uint32_t)k0 * B_ROW_B;
            ldmBT(bfr[0], bAddr);        // n-tiles 0,1
            ldmBT(bfr[1], bAddr + 32);   // n-tiles 2,3
            #pragma unroll
            for (int mt = 0; mt < 4; ++mt)
                #pragma unroll
                for (int nt = 0; nt < 4; ++nt)
                    mma16816(acc[mt][nt], afr[mt],
                             bfr[nt >> 1][(nt & 1) * 2], bfr[nt >> 1][(nt & 1) * 2 + 1]);
        }
    }

    // ---- epilogue: bias + relu ----
    const int row0 = mblk * BM + wm * 64 + (lane >> 2);
    const int col0 = pblk * BN + wn * 32 + (lane & 3) * 2;
    #pragma unroll
    for (int mt = 0; mt < 4; ++mt) {
        const int r = row0 + mt * 16;
        const float bv0 = bias[r];
        const float bv1 = bias[r + 8];
        float* p0 = out + ((size_t)nb * GM + r) * GN + col0;
        float* p1 = p0 + (size_t)8 * GN;
        #pragma unroll
        for (int nt = 0; nt < 4; ++nt) {
            float2 v0, v1;
            v0.x = fmaxf(acc[mt][nt][0] + bv0, 0.0f);
            v0.y = fmaxf(acc[mt][nt][1] + bv0, 0.0f);
            v1.x = fmaxf(acc[mt][nt][2] + bv1, 0.0f);
            v1.y = fmaxf(acc[mt][nt][3] + bv1, 0.0f);
            *(float2*)(p0 + nt * 8) = v0;
            *(float2*)(p1 + nt * 8) = v1;
        }
    }
}

// ---------------------------------------------------------------------------
extern "C" void kernel_launch(void* const* d_in, const int* in_sizes, int n_in,
                              void* d_out, int out_size) {
    const float* fea  = (const float*)d_in[0];
    const float* W    = (const float*)d_in[1];
    const float* bias = (const float*)d_in[2];
    float* out = (float*)d_out;

    static bool attr_set = false;
    if (!attr_set) {
        cudaFuncSetAttribute(gemm_kernel, cudaFuncAttributeMaxDynamicSharedMemorySize, SMEM_B);
        attr_set = true;
    }

    pack_w_kernel<<<(GM * GK + 255) / 256, 256>>>(W);
    gemm_kernel<<<dim3(NMB, NPB, NB), 256, SMEM_B>>>(fea, bias, out);
}